// round 2
// baseline (speedup 1.0000x reference)
#include <cuda_runtime.h>
#include <cstdint>

// PolynomialFeatures: out[b] = concat(x[b], x[b, idx_a] * x[b, idx_b])
// x: [B, F=256] fp32, idx_a/idx_b: [npairs] int32, out: [B, F+npairs] fp32
//
// Store-bandwidth-bound (~539 MB out). Strategy:
//  - 4 rows per block: x rows staged in smem (4 KB), idx int4 loads reused 4x
//  - float4 stores, coalesced across the warp
//  - idx arrays (260 KB) stay L2-resident across the whole grid

#define ROWS_PER_BLOCK 4
#define F_FEAT 256
#define THREADS 256

__global__ __launch_bounds__(THREADS)
void poly_features_kernel(const float* __restrict__ x,
                          const int*   __restrict__ idx_a,
                          const int*   __restrict__ idx_b,
                          float*       __restrict__ out,
                          int B, int npairs)
{
    __shared__ float sx[ROWS_PER_BLOCK][F_FEAT];

    const int row0 = blockIdx.x * ROWS_PER_BLOCK;
    const int tid  = threadIdx.x;
    const size_t out_stride = (size_t)(F_FEAT + npairs);

    // Stage rows into smem and copy x -> out[:, :F] at the same time.
    #pragma unroll
    for (int r = 0; r < ROWS_PER_BLOCK; r++) {
        int row = row0 + r;
        if (row < B) {
            float v = x[(size_t)row * F_FEAT + tid];
            sx[r][tid] = v;
            out[(size_t)row * out_stride + tid] = v;
        }
    }
    __syncthreads();

    const int nq = npairs >> 2;  // number of int4/float4 groups (32640/4 = 8160)
    const int4* __restrict__ ia4 = (const int4*)idx_a;
    const int4* __restrict__ ib4 = (const int4*)idx_b;

    const int rows_here = min(ROWS_PER_BLOCK, B - row0);

    for (int q = tid; q < nq; q += THREADS) {
        int4 a = ia4[q];
        int4 b = ib4[q];
        #pragma unroll
        for (int r = 0; r < ROWS_PER_BLOCK; r++) {
            if (r < rows_here) {
                float4 v;
                v.x = sx[r][a.x] * sx[r][b.x];
                v.y = sx[r][a.y] * sx[r][b.y];
                v.z = sx[r][a.z] * sx[r][b.z];
                v.w = sx[r][a.w] * sx[r][b.w];
                float4* dst = (float4*)(out + (size_t)(row0 + r) * out_stride + F_FEAT);
                dst[q] = v;
            }
        }
    }

    // Tail for npairs not divisible by 4 (32640 % 4 == 0, but stay general).
    for (int p = nq * 4 + tid; p < npairs; p += THREADS) {
        int ai = idx_a[p];
        int bi = idx_b[p];
        #pragma unroll
        for (int r = 0; r < ROWS_PER_BLOCK; r++) {
            if (r < rows_here) {
                out[(size_t)(row0 + r) * out_stride + F_FEAT + p] = sx[r][ai] * sx[r][bi];
            }
        }
    }
}

extern "C" void kernel_launch(void* const* d_in, const int* in_sizes, int n_in,
                              void* d_out, int out_size)
{
    const float* x     = (const float*)d_in[0];
    const int*   idx_a = (const int*)d_in[1];
    const int*   idx_b = (const int*)d_in[2];
    float*       out   = (float*)d_out;

    const int F = F_FEAT;
    const int B = in_sizes[0] / F;
    const int npairs = in_sizes[1];

    const int grid = (B + ROWS_PER_BLOCK - 1) / ROWS_PER_BLOCK;
    poly_features_kernel<<<grid, THREADS>>>(x, idx_a, idx_b, out, B, npairs);
}

// round 3
// speedup vs baseline: 1.0976x; 1.0976x over previous
#include <cuda_runtime.h>
#include <cstdint>

// PolynomialFeatures: out[b] = concat(x[b], x[b, idx_a] * x[b, idx_b])
// x: [B, 256] fp32, out: [B, 256+32640] fp32.
//
// Fast path exploits that (idx_a, idx_b) = combinations(range(256), 2) in
// lexicographic order: run i covers j in [i+1, 256), base(i)=255i - i(i-1)/2.
// Per run: broadcast smem read of x[i] + consecutive (conflict-free) reads of
// x[j] + coalesced stores. Runs i and 254-i sum to exactly 256 elements, so
// each of 128 iterations keeps all 256 threads busy.

#define ROWS_PER_BLOCK 4
#define F_FEAT 256
#define THREADS 256
#define NPAIRS_EXPECTED 32640   // 256*255/2

__device__ __forceinline__ int run_base(int i) {
    // sum_{k=0}^{i-1} (255-k) = 255*i - i*(i-1)/2
    return i * 255 - (i * (i - 1)) / 2;
}

__global__ __launch_bounds__(THREADS)
void poly_features_fast(const float* __restrict__ x,
                        float*       __restrict__ out,
                        int B, int npairs)
{
    __shared__ float sx[ROWS_PER_BLOCK][F_FEAT];

    const int row0 = blockIdx.x * ROWS_PER_BLOCK;
    const int t    = threadIdx.x;
    const size_t out_stride = (size_t)(F_FEAT + npairs);
    const int rows_here = min(ROWS_PER_BLOCK, B - row0);

    // Stage rows into smem and copy x -> out[:, :F].
    #pragma unroll
    for (int r = 0; r < ROWS_PER_BLOCK; r++) {
        if (r < rows_here) {
            float v = x[(size_t)(row0 + r) * F_FEAT + t];
            sx[r][t] = v;
            out[(size_t)(row0 + r) * out_stride + t] = v;
        }
    }
    __syncthreads();

    // Precompute per-row output base pointers (crossed region).
    float* ob[ROWS_PER_BLOCK];
    #pragma unroll
    for (int r = 0; r < ROWS_PER_BLOCK; r++)
        ob[r] = out + (size_t)(row0 + r) * out_stride + F_FEAT;

    #pragma unroll 4
    for (int it = 0; it < 128; it++) {
        const int L = 255 - it;        // length of run `it`
        int i, j, pos;
        if (t < L) {                   // front run: i = it
            i   = it;
            j   = it + 1 + t;
            pos = run_base(it) + t;
        } else {                       // back run: i = 254 - it
            const int i2 = 254 - it;
            const int u  = t - L;
            i   = i2;
            j   = i2 + 1 + u;
            pos = run_base(i2) + u;
        }
        // (it==127: both halves write the same run with identical values —
        //  benign duplicate stores, keeps the loop branch-free.)
        #pragma unroll
        for (int r = 0; r < ROWS_PER_BLOCK; r++) {
            if (r < rows_here) {
                ob[r][pos] = sx[r][i] * sx[r][j];   // broadcast * conflict-free
            }
        }
    }
}

// ---- Generic fallback (idx-driven), used only if npairs != 32640 ----
__global__ __launch_bounds__(THREADS)
void poly_features_generic(const float* __restrict__ x,
                           const int*   __restrict__ idx_a,
                           const int*   __restrict__ idx_b,
                           float*       __restrict__ out,
                           int B, int npairs)
{
    __shared__ float sx[ROWS_PER_BLOCK][F_FEAT];
    const int row0 = blockIdx.x * ROWS_PER_BLOCK;
    const int tid  = threadIdx.x;
    const size_t out_stride = (size_t)(F_FEAT + npairs);

    #pragma unroll
    for (int r = 0; r < ROWS_PER_BLOCK; r++) {
        int row = row0 + r;
        if (row < B) {
            float v = x[(size_t)row * F_FEAT + tid];
            sx[r][tid] = v;
            out[(size_t)row * out_stride + tid] = v;
        }
    }
    __syncthreads();

    const int rows_here = min(ROWS_PER_BLOCK, B - row0);
    for (int p = tid; p < npairs; p += THREADS) {
        int ai = idx_a[p];
        int bi = idx_b[p];
        #pragma unroll
        for (int r = 0; r < ROWS_PER_BLOCK; r++) {
            if (r < rows_here)
                out[(size_t)(row0 + r) * out_stride + F_FEAT + p] = sx[r][ai] * sx[r][bi];
        }
    }
}

extern "C" void kernel_launch(void* const* d_in, const int* in_sizes, int n_in,
                              void* d_out, int out_size)
{
    const float* x     = (const float*)d_in[0];
    const int*   idx_a = (const int*)d_in[1];
    const int*   idx_b = (const int*)d_in[2];
    float*       out   = (float*)d_out;

    const int B = in_sizes[0] / F_FEAT;
    const int npairs = in_sizes[1];
    const int grid = (B + ROWS_PER_BLOCK - 1) / ROWS_PER_BLOCK;

    if (npairs == NPAIRS_EXPECTED) {
        poly_features_fast<<<grid, THREADS>>>(x, out, B, npairs);
    } else {
        poly_features_generic<<<grid, THREADS>>>(x, idx_a, idx_b, out, B, npairs);
    }
}

// round 4
// speedup vs baseline: 1.7549x; 1.5988x over previous
#include <cuda_runtime.h>
#include <cstdint>

// PolynomialFeatures: out[b] = concat(x[b], x[b, idx_a] * x[b, idx_b])
// x: [B, 256] fp32, out: [B, 256+32640] fp32.
//
// Fast path: (idx_a, idx_b) = combinations(range(256), 2) lexicographic.
// Crossed region flattened into float4 groups -> STG.128 coalesced stores.
// Run index recovered analytically: i = floor((511 - sqrt(511^2 - 8p))/2),
// j = p - base(i) + i + 1. Interleaved smem layout makes the stride-4
// j-gather bank-conflict-free.

#define ROWS_PER_BLOCK 4
#define F_FEAT 256
#define THREADS 256
#define NPAIRS_EXPECTED 32640   // 256*255/2
#define NGROUPS 8160            // 32640 / 4
#define ILS 72                  // interleave stride (72 % 32 == 8 -> conflict-free)

__device__ __forceinline__ int pbase(int i) {
    // start of run i: sum_{k<i} (255-k) = 255*i - i*(i-1)/2
    return i * 255 - ((i * (i - 1)) >> 1);
}
__device__ __forceinline__ int ilpos(int j) {
    return (j & 3) * ILS + (j >> 2);
}

__global__ __launch_bounds__(THREADS)
void poly_features_v3(const float* __restrict__ x,
                      float*       __restrict__ out,
                      int B)
{
    __shared__ float sx[ROWS_PER_BLOCK][4 * ILS];

    const int row0 = blockIdx.x * ROWS_PER_BLOCK;
    const int t    = threadIdx.x;
    const size_t ostride = (size_t)(F_FEAT + NPAIRS_EXPECTED);
    const int rows_here = min(ROWS_PER_BLOCK, B - row0);

    // Stage rows into interleaved smem; copy x -> out[:, :F].
    #pragma unroll
    for (int r = 0; r < ROWS_PER_BLOCK; r++) {
        if (r < rows_here) {
            float v = x[(size_t)(row0 + r) * F_FEAT + t];
            sx[r][ilpos(t)] = v;
            out[(size_t)(row0 + r) * ostride + t] = v;
        }
    }
    __syncthreads();

    float* ob[ROWS_PER_BLOCK];
    #pragma unroll
    for (int r = 0; r < ROWS_PER_BLOCK; r++)
        ob[r] = out + (size_t)(row0 + r) * ostride + F_FEAT;

    for (int g = t; g < NGROUPS; g += THREADS) {
        const int p = g << 2;

        // Invert run index for p (sqrt guess + exact integer fixups).
        int i = (int)((511.0f - sqrtf((float)(261121 - 8 * p))) * 0.5f);
        if (i < 0) i = 0;
        while (pbase(i + 1) <= p) ++i;
        while (i > 0 && pbase(i) > p) --i;

        // Per-element (i, j); i only ever advances within the group.
        int ia[4], ja[4];
        #pragma unroll
        for (int e = 0; e < 4; e++) {
            const int pe = p + e;
            while (pbase(i + 1) <= pe) ++i;
            const int j = pe - pbase(i) + i + 1;
            ia[e] = ilpos(i);
            ja[e] = ilpos(j);
        }

        #pragma unroll
        for (int r = 0; r < ROWS_PER_BLOCK; r++) {
            if (r < rows_here) {
                float4 v;
                v.x = sx[r][ia[0]] * sx[r][ja[0]];
                v.y = sx[r][ia[1]] * sx[r][ja[1]];
                v.z = sx[r][ia[2]] * sx[r][ja[2]];
                v.w = sx[r][ia[3]] * sx[r][ja[3]];
                *(float4*)(ob[r] + p) = v;   // 16B-aligned: p%4==0, row offsets 16B-aligned
            }
        }
    }
}

// ---- Generic fallback (idx-driven), used only if npairs != 32640 ----
__global__ __launch_bounds__(THREADS)
void poly_features_generic(const float* __restrict__ x,
                           const int*   __restrict__ idx_a,
                           const int*   __restrict__ idx_b,
                           float*       __restrict__ out,
                           int B, int npairs)
{
    __shared__ float sxl[ROWS_PER_BLOCK][F_FEAT];
    const int row0 = blockIdx.x * ROWS_PER_BLOCK;
    const int tid  = threadIdx.x;
    const size_t out_stride = (size_t)(F_FEAT + npairs);

    #pragma unroll
    for (int r = 0; r < ROWS_PER_BLOCK; r++) {
        int row = row0 + r;
        if (row < B) {
            float v = x[(size_t)row * F_FEAT + tid];
            sxl[r][tid] = v;
            out[(size_t)row * out_stride + tid] = v;
        }
    }
    __syncthreads();

    const int rows_here = min(ROWS_PER_BLOCK, B - row0);
    for (int p = tid; p < npairs; p += THREADS) {
        int ai = idx_a[p];
        int bi = idx_b[p];
        #pragma unroll
        for (int r = 0; r < ROWS_PER_BLOCK; r++) {
            if (r < rows_here)
                out[(size_t)(row0 + r) * out_stride + F_FEAT + p] = sxl[r][ai] * sxl[r][bi];
        }
    }
}

extern "C" void kernel_launch(void* const* d_in, const int* in_sizes, int n_in,
                              void* d_out, int out_size)
{
    const float* x     = (const float*)d_in[0];
    const int*   idx_a = (const int*)d_in[1];
    const int*   idx_b = (const int*)d_in[2];
    float*       out   = (float*)d_out;

    const int B = in_sizes[0] / F_FEAT;
    const int npairs = in_sizes[1];
    const int grid = (B + ROWS_PER_BLOCK - 1) / ROWS_PER_BLOCK;

    if (npairs == NPAIRS_EXPECTED) {
        poly_features_v3<<<grid, THREADS>>>(x, out, B);
    } else {
        poly_features_generic<<<grid, THREADS>>>(x, idx_a, idx_b, out, B, npairs);
    }
}

// round 5
// speedup vs baseline: 1.8696x; 1.0654x over previous
#include <cuda_runtime.h>
#include <cstdint>

// PolynomialFeatures: out[b] = concat(x[b], x[b, idx_a] * x[b, idx_b])
// x: [B, 256] fp32, out: [B, 256+32640] fp32.
//
// v4: feature-major / row-minor smem (sx4[feat] = float4 of 4 rows) so one
// LDS.128 serves all 4 rows -> 8 LDS.128 + 16 FMUL + 4 STG.128 per group
// (vs 32 scalar LDS before). j-interleaved layout keeps the stride-4 ja
// gather conflict-free. Indices recovered analytically (no idx-array reads).

#define ROWS_PER_BLOCK 4
#define F_FEAT 256
#define THREADS 256
#define NPAIRS_EXPECTED 32640   // 256*255/2
#define NGROUPS 8160            // 32640 / 4

__device__ __forceinline__ int pbase(int i) {
    // start of run i: 255*i - i*(i-1)/2
    return i * 255 - ((i * (i - 1)) >> 1);
}
// interleave: consecutive-by-4 features land in adjacent float4 slots
__device__ __forceinline__ int il(int j) {
    return (j >> 2) + (j & 3) * 64;
}

__global__ __launch_bounds__(THREADS)
void poly_features_v4(const float* __restrict__ x,
                      float*       __restrict__ out,
                      int B)
{
    __shared__ float4 sx4[F_FEAT];   // sx4[il(j)] = {row0..row3} value of feature j

    const int row0 = blockIdx.x * ROWS_PER_BLOCK;
    const int t    = threadIdx.x;
    const size_t ostride = (size_t)(F_FEAT + NPAIRS_EXPECTED);
    const int rows_here = min(ROWS_PER_BLOCK, B - row0);
    const bool full = (rows_here == ROWS_PER_BLOCK);

    // Stage: feature t for the 4 rows -> one float4; also copy x -> out[:, :F].
    {
        float v0 = 0.f, v1 = 0.f, v2 = 0.f, v3 = 0.f;
        v0 = x[(size_t)(row0 + 0) * F_FEAT + t];
        out[(size_t)(row0 + 0) * ostride + t] = v0;
        if (full || rows_here > 1) { v1 = x[(size_t)(row0 + 1) * F_FEAT + t];
                                     out[(size_t)(row0 + 1) * ostride + t] = v1; }
        if (full || rows_here > 2) { v2 = x[(size_t)(row0 + 2) * F_FEAT + t];
                                     out[(size_t)(row0 + 2) * ostride + t] = v2; }
        if (full)                  { v3 = x[(size_t)(row0 + 3) * F_FEAT + t];
                                     out[(size_t)(row0 + 3) * ostride + t] = v3; }
        sx4[il(t)] = make_float4(v0, v1, v2, v3);
    }
    __syncthreads();

    float* ob0 = out + (size_t)(row0 + 0) * ostride + F_FEAT;
    float* ob1 = out + (size_t)(row0 + 1) * ostride + F_FEAT;
    float* ob2 = out + (size_t)(row0 + 2) * ostride + F_FEAT;
    float* ob3 = out + (size_t)(row0 + 3) * ostride + F_FEAT;

    for (int g = t; g < NGROUPS; g += THREADS) {
        const int p = g << 2;

        // Invert run index (sqrt estimate + exact integer fixups).
        int i = (int)((511.0f - sqrtf((float)(261121 - 8 * p))) * 0.5f);
        if (i < 0) i = 0;
        while (pbase(i + 1) <= p) ++i;
        while (i > 0 && pbase(i) > p) --i;

        int iai[4], jai[4];
        #pragma unroll
        for (int e = 0; e < 4; e++) {
            const int pe = p + e;
            while (pbase(i + 1) <= pe) ++i;
            const int j = pe - pbase(i) + i + 1;
            iai[e] = il(i);
            jai[e] = il(j);
        }

        // One LDS.128 per feature serves all 4 rows.
        const float4 a0 = sx4[iai[0]], b0 = sx4[jai[0]];
        const float4 a1 = sx4[iai[1]], b1 = sx4[jai[1]];
        const float4 a2 = sx4[iai[2]], b2 = sx4[jai[2]];
        const float4 a3 = sx4[iai[3]], b3 = sx4[jai[3]];

        const float4 v0 = make_float4(a0.x*b0.x, a1.x*b1.x, a2.x*b2.x, a3.x*b3.x);
        const float4 v1 = make_float4(a0.y*b0.y, a1.y*b1.y, a2.y*b2.y, a3.y*b3.y);
        const float4 v2 = make_float4(a0.z*b0.z, a1.z*b1.z, a2.z*b2.z, a3.z*b3.z);
        const float4 v3 = make_float4(a0.w*b0.w, a1.w*b1.w, a2.w*b2.w, a3.w*b3.w);

        *(float4*)(ob0 + p) = v0;
        if (full) {
            *(float4*)(ob1 + p) = v1;
            *(float4*)(ob2 + p) = v2;
            *(float4*)(ob3 + p) = v3;
        } else {
            if (rows_here > 1) *(float4*)(ob1 + p) = v1;
            if (rows_here > 2) *(float4*)(ob2 + p) = v2;
        }
    }
}

// ---- Generic fallback (idx-driven), used only if npairs != 32640 ----
__global__ __launch_bounds__(THREADS)
void poly_features_generic(const float* __restrict__ x,
                           const int*   __restrict__ idx_a,
                           const int*   __restrict__ idx_b,
                           float*       __restrict__ out,
                           int B, int npairs)
{
    __shared__ float sxl[ROWS_PER_BLOCK][F_FEAT];
    const int row0 = blockIdx.x * ROWS_PER_BLOCK;
    const int tid  = threadIdx.x;
    const size_t out_stride = (size_t)(F_FEAT + npairs);

    #pragma unroll
    for (int r = 0; r < ROWS_PER_BLOCK; r++) {
        int row = row0 + r;
        if (row < B) {
            float v = x[(size_t)row * F_FEAT + tid];
            sxl[r][tid] = v;
            out[(size_t)row * out_stride + tid] = v;
        }
    }
    __syncthreads();

    const int rows_here = min(ROWS_PER_BLOCK, B - row0);
    for (int p = tid; p < npairs; p += THREADS) {
        int ai = idx_a[p];
        int bi = idx_b[p];
        #pragma unroll
        for (int r = 0; r < ROWS_PER_BLOCK; r++) {
            if (r < rows_here)
                out[(size_t)(row0 + r) * out_stride + F_FEAT + p] = sxl[r][ai] * sxl[r][bi];
        }
    }
}

extern "C" void kernel_launch(void* const* d_in, const int* in_sizes, int n_in,
                              void* d_out, int out_size)
{
    const float* x     = (const float*)d_in[0];
    const int*   idx_a = (const int*)d_in[1];
    const int*   idx_b = (const int*)d_in[2];
    float*       out   = (float*)d_out;

    const int B = in_sizes[0] / F_FEAT;
    const int npairs = in_sizes[1];
    const int grid = (B + ROWS_PER_BLOCK - 1) / ROWS_PER_BLOCK;

    if (npairs == NPAIRS_EXPECTED) {
        poly_features_v4<<<grid, THREADS>>>(x, out, B);
    } else {
        poly_features_generic<<<grid, THREADS>>>(x, idx_a, idx_b, out, B, npairs);
    }
}